// round 3
// baseline (speedup 1.0000x reference)
#include <cuda_runtime.h>
#include <cmath>

#define NLV 16
#define TABLE_SIZE (1u << 19)
#define HMASK (TABLE_SIZE - 1u)
#define P1 2654435761u
#define P2 805459861u

#define NP_MAX 1000000
#define GRID_BITS 5
#define GRID_RES (1 << GRID_BITS)          // 32
#define NBINS (1 << (3 * GRID_BITS))       // 32768
#define SCAN_BLOCK 512
#define NSCAN_BLOCKS (NBINS / SCAN_BLOCK)  // 64

struct ResParams { int r[NLV]; };

// ---- scratch (static device globals; no allocation) ----
__device__ unsigned g_hist[NBINS];
__device__ unsigned g_blocksums[NSCAN_BLOCKS];
__device__ float4   g_pts[NP_MAX];   // x,y,z, perm-as-bits

// ---------------- Morton ----------------
__device__ __forceinline__ unsigned expand_bits(unsigned v) {
    v &= 0x3FFu;
    v = (v | (v << 16)) & 0x030000FFu;
    v = (v | (v << 8))  & 0x0300F00Fu;
    v = (v | (v << 4))  & 0x030C30C3u;
    v = (v | (v << 2))  & 0x09249249u;
    return v;
}
__device__ __forceinline__ unsigned morton3(float x, float y, float z) {
    unsigned ix = min((unsigned)(x * (float)GRID_RES), (unsigned)(GRID_RES - 1));
    unsigned iy = min((unsigned)(y * (float)GRID_RES), (unsigned)(GRID_RES - 1));
    unsigned iz = min((unsigned)(z * (float)GRID_RES), (unsigned)(GRID_RES - 1));
    return (expand_bits(ix) << 2) | (expand_bits(iy) << 1) | expand_bits(iz);
}

// ---------------- sort pipeline ----------------
__global__ void k_hist(const float* __restrict__ coords, int n) {
    int i = blockIdx.x * blockDim.x + threadIdx.x;
    if (i >= n) return;
    unsigned key = morton3(coords[3 * i], coords[3 * i + 1], coords[3 * i + 2]);
    atomicAdd(&g_hist[key], 1u);
}

__global__ void k_scan1() {
    __shared__ unsigned s[SCAN_BLOCK];
    int t = threadIdx.x;
    int gi = blockIdx.x * SCAN_BLOCK + t;
    unsigned v = g_hist[gi];
    s[t] = v;
    __syncthreads();
    for (int o = 1; o < SCAN_BLOCK; o <<= 1) {
        unsigned u = (t >= o) ? s[t - o] : 0u;
        __syncthreads();
        s[t] += u;
        __syncthreads();
    }
    g_hist[gi] = s[t] - v;  // exclusive
    if (t == SCAN_BLOCK - 1) g_blocksums[blockIdx.x] = s[t];
}

__global__ void k_scan2() {
    __shared__ unsigned s[NSCAN_BLOCKS];
    int t = threadIdx.x;
    unsigned v = g_blocksums[t];
    s[t] = v;
    __syncthreads();
    for (int o = 1; o < NSCAN_BLOCKS; o <<= 1) {
        unsigned u = (t >= o) ? s[t - o] : 0u;
        __syncthreads();
        s[t] += u;
        __syncthreads();
    }
    g_blocksums[t] = s[t] - v;  // exclusive
}

__global__ void k_scan3() {
    int gi = blockIdx.x * SCAN_BLOCK + threadIdx.x;
    g_hist[gi] += g_blocksums[blockIdx.x];
}

__global__ void k_scatter(const float* __restrict__ coords, int n) {
    int i = blockIdx.x * blockDim.x + threadIdx.x;
    if (i >= n) return;
    float x = coords[3 * i], y = coords[3 * i + 1], z = coords[3 * i + 2];
    unsigned key = morton3(x, y, z);
    unsigned pos = atomicAdd(&g_hist[key], 1u);
    g_pts[pos] = make_float4(x, y, z, __int_as_float(i));  // one STG.128
}

// ---------------- main kernel ----------------
// block = 512 threads = 16 warps; warp w handles level w for 32 sorted points.
__global__ __launch_bounds__(512)
void hashgrid_main(const float* __restrict__ tables,
                   float* __restrict__ out,
                   ResParams rp, int n_points)
{
    __shared__ float s_pt[32 * 4];      // x,y,z,permbits per point
    __shared__ float s_out[32][33];

    int t = threadIdx.x;
    int w = t >> 5;          // level
    int lane = t & 31;       // point within tile
    int base = blockIdx.x * 32;

    // cooperative coalesced load of 32 float4 (512B)
    if (t < 128) {
        int idx = base * 4 + t;
        s_pt[t] = (idx < n_points * 4) ? ((const float*)g_pts)[idx] : 0.0f;
    }
    __syncthreads();

    int pi = base + lane;
    if (pi < n_points) {
        float cx = s_pt[lane * 4 + 0];
        float cy = s_pt[lane * 4 + 1];
        float cz = s_pt[lane * 4 + 2];

        int ires = rp.r[w];
        float res = (float)ires;

        float sx = cx * res, sy = cy * res, sz = cz * res;
        float fx = floorf(sx), fy = floorf(sy), fz = floorf(sz);
        float wx = sx - fx, wy = sy - fy, wz = sz - fz;

        // exact integer corner math; mod 2^19 via uint32 wrap
        unsigned ux = (unsigned)((int)fx * ires);
        unsigned uy = (unsigned)((int)fy * ires) * P1;
        unsigned uz = (unsigned)((int)fz * ires) * P2;
        unsigned dx = (unsigned)ires;
        unsigned dy = (unsigned)ires * P1;
        unsigned dz = (unsigned)ires * P2;

        const float2* __restrict__ tbl =
            (const float2*)tables + (size_t)w * TABLE_SIZE;

        float2 f000 = __ldg(tbl + ((ux      + uy      + uz     ) & HMASK));
        float2 f001 = __ldg(tbl + ((ux      + uy      + uz + dz) & HMASK));
        float2 f010 = __ldg(tbl + ((ux      + uy + dy + uz     ) & HMASK));
        float2 f011 = __ldg(tbl + ((ux      + uy + dy + uz + dz) & HMASK));
        float2 f100 = __ldg(tbl + ((ux + dx + uy      + uz     ) & HMASK));
        float2 f101 = __ldg(tbl + ((ux + dx + uy      + uz + dz) & HMASK));
        float2 f110 = __ldg(tbl + ((ux + dx + uy + dy + uz     ) & HMASK));
        float2 f111 = __ldg(tbl + ((ux + dx + uy + dy + uz + dz) & HMASK));

        float ex = 1.0f - wx, ey = 1.0f - wy, ez = 1.0f - wz;

        float c00a = f000.x * ex + f100.x * wx;
        float c00b = f000.y * ex + f100.y * wx;
        float c01a = f001.x * ex + f101.x * wx;
        float c01b = f001.y * ex + f101.y * wx;
        float c10a = f010.x * ex + f110.x * wx;
        float c10b = f010.y * ex + f110.y * wx;
        float c11a = f011.x * ex + f111.x * wx;
        float c11b = f011.y * ex + f111.y * wx;

        float c0a = c00a * ey + c10a * wy;
        float c0b = c00b * ey + c10b * wy;
        float c1a = c01a * ey + c11a * wy;
        float c1b = c01b * ey + c11b * wy;

        s_out[lane][2 * w]     = c0a * ez + c1a * wz;
        s_out[lane][2 * w + 1] = c0b * ez + c1b * wz;
    }
    __syncthreads();

    // coalesced writeout: warp w writes rows w and w+16 (128B contiguous each)
    #pragma unroll
    for (int it = 0; it < 2; ++it) {
        int row = w + 16 * it;
        if (base + row < n_points) {
            int gp = __float_as_int(s_pt[row * 4 + 3]);
            out[(size_t)gp * 32 + lane] = s_out[row][lane];
        }
    }
}

// ---------------- launch ----------------
extern "C" void kernel_launch(void* const* d_in, const int* in_sizes, int n_in,
                              void* d_out, int out_size)
{
    const float* coords = (const float*)d_in[0];
    const float* tables = (const float*)d_in[1];
    float* out = (float*)d_out;
    int n_points = in_sizes[0] / 3;

    ResParams rp;
    double g = std::log(512.0 / 16.0) / 15.0;
    for (int l = 0; l < NLV; ++l)
        rp.r[l] = (int)std::floor(16.0 * std::exp((double)l * g));

    void* hist_ptr = nullptr;
    cudaGetSymbolAddress(&hist_ptr, g_hist);
    cudaMemsetAsync(hist_ptr, 0, NBINS * sizeof(unsigned));

    int b = 256;
    int gpts = (n_points + b - 1) / b;
    k_hist<<<gpts, b>>>(coords, n_points);
    k_scan1<<<NSCAN_BLOCKS, SCAN_BLOCK>>>();
    k_scan2<<<1, NSCAN_BLOCKS>>>();
    k_scan3<<<NSCAN_BLOCKS, SCAN_BLOCK>>>();
    k_scatter<<<gpts, b>>>(coords, n_points);

    int ntiles = (n_points + 31) / 32;
    hashgrid_main<<<ntiles, 512>>>(tables, out, rp, n_points);
}

// round 4
// speedup vs baseline: 1.0765x; 1.0765x over previous
#include <cuda_runtime.h>
#include <cmath>

#define NLV 16
#define TABLE_SIZE (1u << 19)
#define HMASK (TABLE_SIZE - 1u)
#define P1 2654435761u
#define P2 805459861u

#define NP_MAX 1000000
#define GRID_BITS 6
#define GRID_RES (1 << GRID_BITS)          // 64
#define NBINS (1 << (3 * GRID_BITS))       // 262144
#define SCAN_BLOCK 512
#define NSCAN_BLOCKS (NBINS / SCAN_BLOCK)  // 512

struct ResParams { int r[NLV]; };

// ---- scratch (static device globals; no allocation) ----
__device__ unsigned g_hist[NBINS];
__device__ unsigned g_blocksums[NSCAN_BLOCKS];
__device__ float4   g_pts[NP_MAX];   // x,y,z, perm-as-bits

// ---------------- Morton ----------------
__device__ __forceinline__ unsigned expand_bits(unsigned v) {
    v &= 0x3FFu;
    v = (v | (v << 16)) & 0x030000FFu;
    v = (v | (v << 8))  & 0x0300F00Fu;
    v = (v | (v << 4))  & 0x030C30C3u;
    v = (v | (v << 2))  & 0x09249249u;
    return v;
}
__device__ __forceinline__ unsigned morton3(float x, float y, float z) {
    unsigned ix = min((unsigned)(x * (float)GRID_RES), (unsigned)(GRID_RES - 1));
    unsigned iy = min((unsigned)(y * (float)GRID_RES), (unsigned)(GRID_RES - 1));
    unsigned iz = min((unsigned)(z * (float)GRID_RES), (unsigned)(GRID_RES - 1));
    return (expand_bits(ix) << 2) | (expand_bits(iy) << 1) | expand_bits(iz);
}

// ---------------- sort pipeline ----------------
__global__ void k_hist(const float* __restrict__ coords, int n) {
    int i = blockIdx.x * blockDim.x + threadIdx.x;
    if (i >= n) return;
    unsigned key = morton3(coords[3 * i], coords[3 * i + 1], coords[3 * i + 2]);
    atomicAdd(&g_hist[key], 1u);
}

__global__ void k_scan1() {
    __shared__ unsigned s[SCAN_BLOCK];
    int t = threadIdx.x;
    int gi = blockIdx.x * SCAN_BLOCK + t;
    unsigned v = g_hist[gi];
    s[t] = v;
    __syncthreads();
    for (int o = 1; o < SCAN_BLOCK; o <<= 1) {
        unsigned u = (t >= o) ? s[t - o] : 0u;
        __syncthreads();
        s[t] += u;
        __syncthreads();
    }
    g_hist[gi] = s[t] - v;  // exclusive
    if (t == SCAN_BLOCK - 1) g_blocksums[blockIdx.x] = s[t];
}

__global__ void k_scan2() {
    __shared__ unsigned s[NSCAN_BLOCKS];
    int t = threadIdx.x;
    unsigned v = g_blocksums[t];
    s[t] = v;
    __syncthreads();
    for (int o = 1; o < NSCAN_BLOCKS; o <<= 1) {
        unsigned u = (t >= o) ? s[t - o] : 0u;
        __syncthreads();
        s[t] += u;
        __syncthreads();
    }
    g_blocksums[t] = s[t] - v;  // exclusive
}

__global__ void k_scan3() {
    int gi = blockIdx.x * SCAN_BLOCK + threadIdx.x;
    g_hist[gi] += g_blocksums[blockIdx.x];
}

__global__ void k_scatter(const float* __restrict__ coords, int n) {
    int i = blockIdx.x * blockDim.x + threadIdx.x;
    if (i >= n) return;
    float x = coords[3 * i], y = coords[3 * i + 1], z = coords[3 * i + 2];
    unsigned key = morton3(x, y, z);
    unsigned pos = atomicAdd(&g_hist[key], 1u);
    g_pts[pos] = make_float4(x, y, z, __int_as_float(i));  // one STG.128
}

// ---------------- main kernel ----------------
// block = 512 threads = 16 warps; warp w handles level w for 32 sorted points.
__global__ __launch_bounds__(512)
void hashgrid_main(const float* __restrict__ tables,
                   float* __restrict__ out,
                   ResParams rp, int n_points)
{
    __shared__ float s_pt[32 * 4];      // x,y,z,permbits per point
    __shared__ float s_out[32][33];

    int t = threadIdx.x;
    int w = t >> 5;          // level
    int lane = t & 31;       // point within tile
    int base = blockIdx.x * 32;

    // cooperative coalesced load of 32 float4 (512B)
    if (t < 128) {
        int idx = base * 4 + t;
        s_pt[t] = (idx < n_points * 4) ? ((const float*)g_pts)[idx] : 0.0f;
    }
    __syncthreads();

    int pi = base + lane;
    if (pi < n_points) {
        float cx = s_pt[lane * 4 + 0];
        float cy = s_pt[lane * 4 + 1];
        float cz = s_pt[lane * 4 + 2];

        int ires = rp.r[w];
        float res = (float)ires;

        float sx = cx * res, sy = cy * res, sz = cz * res;
        float fx = floorf(sx), fy = floorf(sy), fz = floorf(sz);
        float wx = sx - fx, wy = sy - fy, wz = sz - fz;

        // exact integer corner math; mod 2^19 via uint32 wrap
        unsigned ux = (unsigned)((int)fx * ires);
        unsigned uy = (unsigned)((int)fy * ires) * P1;
        unsigned uz = (unsigned)((int)fz * ires) * P2;
        unsigned dx = (unsigned)ires;
        unsigned dy = (unsigned)ires * P1;
        unsigned dz = (unsigned)ires * P2;

        const float2* __restrict__ tbl =
            (const float2*)tables + (size_t)w * TABLE_SIZE;

        float2 f000 = __ldg(tbl + ((ux      + uy      + uz     ) & HMASK));
        float2 f001 = __ldg(tbl + ((ux      + uy      + uz + dz) & HMASK));
        float2 f010 = __ldg(tbl + ((ux      + uy + dy + uz     ) & HMASK));
        float2 f011 = __ldg(tbl + ((ux      + uy + dy + uz + dz) & HMASK));
        float2 f100 = __ldg(tbl + ((ux + dx + uy      + uz     ) & HMASK));
        float2 f101 = __ldg(tbl + ((ux + dx + uy      + uz + dz) & HMASK));
        float2 f110 = __ldg(tbl + ((ux + dx + uy + dy + uz     ) & HMASK));
        float2 f111 = __ldg(tbl + ((ux + dx + uy + dy + uz + dz) & HMASK));

        float ex = 1.0f - wx, ey = 1.0f - wy, ez = 1.0f - wz;

        float c00a = f000.x * ex + f100.x * wx;
        float c00b = f000.y * ex + f100.y * wx;
        float c01a = f001.x * ex + f101.x * wx;
        float c01b = f001.y * ex + f101.y * wx;
        float c10a = f010.x * ex + f110.x * wx;
        float c10b = f010.y * ex + f110.y * wx;
        float c11a = f011.x * ex + f111.x * wx;
        float c11b = f011.y * ex + f111.y * wx;

        float c0a = c00a * ey + c10a * wy;
        float c0b = c00b * ey + c10b * wy;
        float c1a = c01a * ey + c11a * wy;
        float c1b = c01b * ey + c11b * wy;

        s_out[lane][2 * w]     = c0a * ez + c1a * wz;
        s_out[lane][2 * w + 1] = c0b * ez + c1b * wz;
    }
    __syncthreads();

    // coalesced writeout: warp w writes rows w and w+16 (128B contiguous each)
    #pragma unroll
    for (int it = 0; it < 2; ++it) {
        int row = w + 16 * it;
        if (base + row < n_points) {
            int gp = __float_as_int(s_pt[row * 4 + 3]);
            out[(size_t)gp * 32 + lane] = s_out[row][lane];
        }
    }
}

// ---------------- launch ----------------
extern "C" void kernel_launch(void* const* d_in, const int* in_sizes, int n_in,
                              void* d_out, int out_size)
{
    const float* coords = (const float*)d_in[0];
    const float* tables = (const float*)d_in[1];
    float* out = (float*)d_out;
    int n_points = in_sizes[0] / 3;

    ResParams rp;
    double g = std::log(512.0 / 16.0) / 15.0;
    for (int l = 0; l < NLV; ++l)
        rp.r[l] = (int)std::floor(16.0 * std::exp((double)l * g));

    void* hist_ptr = nullptr;
    cudaGetSymbolAddress(&hist_ptr, g_hist);
    cudaMemsetAsync(hist_ptr, 0, NBINS * sizeof(unsigned));

    int b = 256;
    int gpts = (n_points + b - 1) / b;
    k_hist<<<gpts, b>>>(coords, n_points);
    k_scan1<<<NSCAN_BLOCKS, SCAN_BLOCK>>>();
    k_scan2<<<1, NSCAN_BLOCKS>>>();
    k_scan3<<<NSCAN_BLOCKS, SCAN_BLOCK>>>();
    k_scatter<<<gpts, b>>>(coords, n_points);

    int ntiles = (n_points + 31) / 32;
    hashgrid_main<<<ntiles, 512>>>(tables, out, rp, n_points);
}